// round 1
// baseline (speedup 1.0000x reference)
#include <cuda_runtime.h>
#include <cstdint>

// ---------------------------------------------------------------------------
// MDescAug: per-query candidate reranking with descriptor augmentation.
//   X:     [50000, 512]  f32
//   Q:     [100, 512]    f32
//   ranks: [50000, 100]  int32 or int64 (probed at runtime)
// Output (f32, concatenated): rerank_final[100,400], res_top[100,400],
//   pre[100,400], x_dba[100,400,512]  -> 20,600,000 elements
// ---------------------------------------------------------------------------

#define NDB  50000
#define NQ   100
#define DIM  512
#define MM   400
#define KTOP 10
#define BETA 0.15f

#define OFF_RERANK 0
#define OFF_RESTOP 40000
#define OFF_PRE    80000
#define OFF_XDBA   120000
#define FULL_OUT   20600000

// Scratch (device globals; no allocation allowed)
__device__ float g_Xs[(size_t)NQ * MM * DIM];     // 82 MB gathered descriptors
__device__ float g_S[(size_t)NQ * MM * MM];       // 64 MB similarity matrices
__device__ int   g_rt[NQ * MM];                   // ranks_trans
__device__ int   g_idx[NQ * MM * KTOP];
__device__ float g_vals[NQ * MM * KTOP];
__device__ float g_restop[NQ * MM];
__device__ int   g_is64;

// ---- helpers: order-preserving float<->uint mapping --------------------------
__device__ __forceinline__ unsigned int ordf(float f) {
    unsigned int u = __float_as_uint(f);
    return (u & 0x80000000u) ? ~u : (u | 0x80000000u);
}
__device__ __forceinline__ float unordf(unsigned int o) {
    return __uint_as_float((o & 0x80000000u) ? (o & 0x7FFFFFFFu) : ~o);
}
// key: value descending, index ascending on ties
__device__ __forceinline__ unsigned long long pack_key(float v, int idx) {
    return ((unsigned long long)ordf(v) << 32) |
           (unsigned long long)(0xFFFFFFFFu - (unsigned int)idx);
}

// ---- probe: is ranks int64 (high words ~all zero) or int32? -----------------
__global__ void probe_kernel(const int* __restrict__ r) {
    __shared__ int cnt;
    if (threadIdx.x == 0) cnt = 0;
    __syncthreads();
    int nz = 0;
    for (int i = threadIdx.x; i < 1024; i += blockDim.x)
        nz += (r[2 * i + 1] != 0);
    atomicAdd(&cnt, nz);
    __syncthreads();
    if (threadIdx.x == 0) g_is64 = (cnt < 100) ? 1 : 0;
}

// ---- gather Xs[q][m][:] = X[ranks[m][q]][:] ---------------------------------
__global__ __launch_bounds__(128) void gather_kernel(const float* __restrict__ X,
                                                     const void* __restrict__ ranks) {
    int m = blockIdx.x, q = blockIdx.y, tid = threadIdx.x;
    int rid;
    if (g_is64) rid = (int)((const long long*)ranks)[(size_t)m * NQ + q];
    else        rid = ((const int*)ranks)[(size_t)m * NQ + q];
    if (tid == 0) g_rt[q * MM + m] = rid;
    const float4* src = (const float4*)(X + (size_t)rid * DIM);
    float4* dst = (float4*)(g_Xs + ((size_t)q * MM + m) * DIM);
    dst[tid] = src[tid];
}

// ---- batched symmetric GEMM: S_q = Xs_q * Xs_q^T (only bi<=bj tile pairs) ---
// 64x64 tile, BK=16, 256 threads, 4x4 per-thread fragments.
__global__ __launch_bounds__(256) void gemm_kernel() {
    int p = blockIdx.x, q = blockIdx.y;
    int bi = 0, bj = 0;
    {
        int t = 0;
        #pragma unroll
        for (int i = 0; i < 7; i++) {
            int c = 7 - i;
            if (p < t + c) { bi = i; bj = i + (p - t); break; }
            t += c;
        }
    }
    const float* A = g_Xs + (size_t)q * MM * DIM;
    float* S = g_S + (size_t)q * MM * MM;

    __shared__ __align__(16) float As[16][68];
    __shared__ __align__(16) float Bs[16][68];

    int tid = threadIdx.x;
    int tx = tid & 15, ty = tid >> 4;
    int lrow = tid >> 2;   // 0..63
    int lseg = tid & 3;    // 0..3
    int arow = bi * 64 + lrow;
    int brow = bj * 64 + lrow;

    float acc[4][4];
    #pragma unroll
    for (int r = 0; r < 4; r++)
        #pragma unroll
        for (int c = 0; c < 4; c++) acc[r][c] = 0.0f;

    const float4 z4 = make_float4(0.f, 0.f, 0.f, 0.f);

    for (int kt = 0; kt < DIM; kt += 16) {
        float4 av = (arow < MM) ? *(const float4*)(A + (size_t)arow * DIM + kt + lseg * 4) : z4;
        float4 bv = (brow < MM) ? *(const float4*)(A + (size_t)brow * DIM + kt + lseg * 4) : z4;
        As[lseg * 4 + 0][lrow] = av.x;
        As[lseg * 4 + 1][lrow] = av.y;
        As[lseg * 4 + 2][lrow] = av.z;
        As[lseg * 4 + 3][lrow] = av.w;
        Bs[lseg * 4 + 0][lrow] = bv.x;
        Bs[lseg * 4 + 1][lrow] = bv.y;
        Bs[lseg * 4 + 2][lrow] = bv.z;
        Bs[lseg * 4 + 3][lrow] = bv.w;
        __syncthreads();
        #pragma unroll
        for (int kk = 0; kk < 16; kk++) {
            float4 a4 = *(const float4*)&As[kk][ty * 4];
            float4 b4 = *(const float4*)&Bs[kk][tx * 4];
            float ar[4] = {a4.x, a4.y, a4.z, a4.w};
            float br[4] = {b4.x, b4.y, b4.z, b4.w};
            #pragma unroll
            for (int r = 0; r < 4; r++)
                #pragma unroll
                for (int c = 0; c < 4; c++)
                    acc[r][c] += ar[r] * br[c];
        }
        __syncthreads();
    }

    int ro = bi * 64 + ty * 4;
    int co = bj * 64 + tx * 4;

    // normal write (upper block)
    #pragma unroll
    for (int r = 0; r < 4; r++) {
        int row = ro + r;
        if (row < MM) {
            if (co + 4 <= MM) {
                float4 v = make_float4(acc[r][0], acc[r][1], acc[r][2], acc[r][3]);
                *(float4*)(S + (size_t)row * MM + co) = v;
            } else {
                #pragma unroll
                for (int c = 0; c < 4; c++)
                    if (co + c < MM) S[(size_t)row * MM + co + c] = acc[r][c];
            }
        }
    }
    // transposed write (lower block) for off-diagonal pairs; rows always <400 since bi<bj => bi<=5
    if (bi != bj) {
        #pragma unroll
        for (int c = 0; c < 4; c++) {
            int col = co + c;
            if (col < MM) {
                float4 v = make_float4(acc[0][c], acc[1][c], acc[2][c], acc[3][c]);
                *(float4*)(S + (size_t)col * MM + ro) = v;
            }
        }
    }
}

// ---- top-10 per row, value desc / index asc tie-break (warp per row) --------
__global__ __launch_bounds__(256) void topk_kernel() {
    int warp = threadIdx.x >> 5, lane = threadIdx.x & 31;
    int row = blockIdx.x * 8 + warp;
    if (row >= NQ * MM) return;
    const float* Srow = g_S + (size_t)row * MM;

    unsigned long long key[13];
    #pragma unroll
    for (int t = 0; t < 13; t++) {
        int c = lane + t * 32;
        key[t] = (c < MM) ? pack_key(Srow[c], c) : 0ULL;
    }
    #pragma unroll
    for (int it = 0; it < KTOP; it++) {
        unsigned long long best = 0;
        #pragma unroll
        for (int t = 0; t < 13; t++) if (key[t] > best) best = key[t];
        #pragma unroll
        for (int off = 16; off > 0; off >>= 1) {
            unsigned long long o = __shfl_xor_sync(0xFFFFFFFFu, best, off);
            if (o > best) best = o;
        }
        if (lane == 0) {
            int c = (int)(0xFFFFFFFFu - (unsigned int)(best & 0xFFFFFFFFu));
            g_idx[row * KTOP + it] = c;
            g_vals[row * KTOP + it] = unordf((unsigned int)(best >> 32));
        }
        #pragma unroll
        for (int t = 0; t < 13; t++) if (key[t] == best) key[t] = 0ULL;
    }
}

// ---- x_dba = (g0 + sum_k 0.15*val_k*g_k) / (1 + 0.15*sum val_k); res_top ----
__global__ __launch_bounds__(128) void xdba_kernel(const float* __restrict__ Qm,
                                                   float* __restrict__ out, int full) {
    int m = blockIdx.x, q = blockIdx.y, tid = threadIdx.x;
    int row = q * MM + m;
    __shared__ int sidx[KTOP];
    __shared__ float sval[KTOP];
    __shared__ float red[128];
    if (tid < KTOP) {
        sidx[tid] = g_idx[row * KTOP + tid];
        sval[tid] = g_vals[row * KTOP + tid];
    }
    __syncthreads();

    const float4* Xq = (const float4*)(g_Xs + (size_t)q * MM * DIM);
    float4 a = Xq[(size_t)sidx[0] * (DIM / 4) + tid];  // w0 = 1.0
    float sumw = 1.0f;
    #pragma unroll
    for (int k = 1; k < KTOP; k++) {
        float w = __fmul_rn(BETA, sval[k]);
        sumw = __fadd_rn(sumw, w);
        float4 v = Xq[(size_t)sidx[k] * (DIM / 4) + tid];
        a.x = __fadd_rn(a.x, __fmul_rn(w, v.x));
        a.y = __fadd_rn(a.y, __fmul_rn(w, v.y));
        a.z = __fadd_rn(a.z, __fmul_rn(w, v.z));
        a.w = __fadd_rn(a.w, __fmul_rn(w, v.w));
    }
    a.x = __fdiv_rn(a.x, sumw);
    a.y = __fdiv_rn(a.y, sumw);
    a.z = __fdiv_rn(a.z, sumw);
    a.w = __fdiv_rn(a.w, sumw);

    if (full)
        *(float4*)(out + OFF_XDBA + (size_t)row * DIM + tid * 4) = a;

    float4 qv = ((const float4*)Qm)[(size_t)q * (DIM / 4) + tid];
    red[tid] = a.x * qv.x + a.y * qv.y + a.z * qv.z + a.w * qv.w;
    __syncthreads();
    #pragma unroll
    for (int s = 64; s > 0; s >>= 1) {
        if (tid < s) red[tid] += red[tid + s];
        __syncthreads();
    }
    if (tid == 0) {
        g_restop[row] = red[0];
        if (full) out[OFF_RESTOP + row] = red[0];
    }
}

// ---- per-query stable descending sort (bitonic over 512) + final outputs ----
__global__ __launch_bounds__(512) void sort_kernel(float* __restrict__ out,
                                                   int full, int out_size) {
    int q = blockIdx.x, tid = threadIdx.x;
    __shared__ unsigned long long sk[512];
    sk[tid] = (tid < MM) ? pack_key(g_restop[q * MM + tid], tid) : 0ULL;
    __syncthreads();
    for (int k = 2; k <= 512; k <<= 1) {
        for (int j = k >> 1; j > 0; j >>= 1) {
            int ixj = tid ^ j;
            if (ixj > tid) {
                unsigned long long a = sk[tid], b = sk[ixj];
                bool desc = (tid & k) == 0;
                if (desc ? (a < b) : (a > b)) { sk[tid] = b; sk[ixj] = a; }
            }
            __syncthreads();
        }
    }
    if (tid < MM) {
        unsigned int msel = 0xFFFFFFFFu - (unsigned int)(sk[tid] & 0xFFFFFFFFu);
        int o0 = q * MM + tid;
        if (o0 < out_size) out[OFF_RERANK + o0] = (float)g_rt[q * MM + msel];
        if (full) out[OFF_PRE + o0] = (float)msel;
    }
}

extern "C" void kernel_launch(void* const* d_in, const int* in_sizes, int n_in,
                              void* d_out, int out_size) {
    const float* X  = (const float*)d_in[0];
    const float* Qm = (const float*)d_in[1];
    const void*  rk = d_in[2];
    float* out = (float*)d_out;
    int full = (out_size >= FULL_OUT) ? 1 : 0;

    probe_kernel<<<1, 256>>>((const int*)rk);
    gather_kernel<<<dim3(MM, NQ), 128>>>(X, rk);
    gemm_kernel<<<dim3(28, NQ), 256>>>();
    topk_kernel<<<(NQ * MM + 7) / 8, 256>>>();
    xdba_kernel<<<dim3(MM, NQ), 128>>>(Qm, out, full);
    sort_kernel<<<NQ, 512>>>(out, full, out_size);
}